// round 8
// baseline (speedup 1.0000x reference)
#include <cuda_runtime.h>

#define BB 4
#define SS 1024
#define HIDD 1024
#define HH 16
#define DD 64
#define MAXP 1024

// Scratch for Q,K,V projections: [B*S, H*D] row-major
__device__ float g_q[BB*SS*HIDD];
__device__ float g_k[BB*SS*HIDD];
__device__ float g_v[BB*SS*HIDD];

// ---------------------------------------------------------------------------
// helpers: tf32 convert + m16n8k8 tf32 mma
// ---------------------------------------------------------------------------
__device__ __forceinline__ unsigned f2tf(float x) {
    unsigned r;
    asm("cvt.rna.tf32.f32 %0, %1;" : "=r"(r) : "f"(x));
    return r;
}
__device__ __forceinline__ uint4 cvt4(float4 v) {
    uint4 r;
    r.x = f2tf(v.x); r.y = f2tf(v.y); r.z = f2tf(v.z); r.w = f2tf(v.w);
    return r;
}
__device__ __forceinline__ void mma8(float* c, const unsigned* a, unsigned b0, unsigned b1) {
    asm volatile(
        "mma.sync.aligned.m16n8k8.row.col.f32.tf32.tf32.f32 "
        "{%0,%1,%2,%3}, {%4,%5,%6,%7}, {%8,%9}, {%0,%1,%2,%3};"
        : "+f"(c[0]), "+f"(c[1]), "+f"(c[2]), "+f"(c[3])
        : "r"(a[0]), "r"(a[1]), "r"(a[2]), "r"(a[3]), "r"(b0), "r"(b1));
}

// ---------------------------------------------------------------------------
// QKV GEMM (tf32 tensor): C[4096,1024] = X @ W + bias, tile 128x128, k-step 16
// 256 threads, 8 warps. Register-prefetch double buffering on global loads.
// ---------------------------------------------------------------------------
#define XS_STR 20    // 20 mod 32 = 4  -> A-frag conflict-free
#define WS_STR 136   // 136 mod 32 = 8 -> B-frag conflict-free

__global__ __launch_bounds__(256) void qkv_gemm(
    const float* __restrict__ X,
    const float* __restrict__ Wq, const float* __restrict__ bq,
    const float* __restrict__ Wk, const float* __restrict__ bk,
    const float* __restrict__ Wv, const float* __restrict__ bv)
{
    const float* Wm; const float* bias; float* out;
    if (blockIdx.z == 0)      { Wm = Wq; bias = bq; out = g_q; }
    else if (blockIdx.z == 1) { Wm = Wk; bias = bk; out = g_k; }
    else                      { Wm = Wv; bias = bv; out = g_v; }

    __shared__ unsigned Xs[128 * XS_STR];
    __shared__ unsigned Ws[16 * WS_STR];

    const int tid = threadIdx.x;
    const int lane = tid & 31, w = tid >> 5;
    const int wrr = w >> 1, wcc = w & 1;
    const int gid = lane >> 2, tin = lane & 3;
    const int m0 = blockIdx.y * 128, n0 = blockIdx.x * 128;

    // per-thread load coordinates (fixed across k-steps)
    const int xm  = tid >> 2,        xk4 = (tid & 3) * 4;        // +r*64 rows
    const int wk  = tid >> 5,        wn4 = (tid & 31) * 4;       // +r*8 k-rows

    float c[2][8][4];
    #pragma unroll
    for (int mt = 0; mt < 2; mt++)
        #pragma unroll
        for (int nt = 0; nt < 8; nt++)
            #pragma unroll
            for (int u = 0; u < 4; u++) c[mt][nt][u] = 0.f;

    // prefetch k0 = 0
    float4 xpre[2], wpre[2];
    #pragma unroll
    for (int r = 0; r < 2; r++) {
        xpre[r] = *reinterpret_cast<const float4*>(
            &X[(size_t)(m0 + xm + r * 64) * HIDD + xk4]);
        wpre[r] = *reinterpret_cast<const float4*>(
            &Wm[(size_t)(wk + r * 8) * HIDD + n0 + wn4]);
    }

    for (int k0 = 0; k0 < HIDD; k0 += 16) {
        // store prefetched tile to smem (tf32)
        #pragma unroll
        for (int r = 0; r < 2; r++) {
            uint4 xv = cvt4(xpre[r]);
            Xs[(xm + r * 64) * XS_STR + xk4 + 0] = xv.x;
            Xs[(xm + r * 64) * XS_STR + xk4 + 1] = xv.y;
            Xs[(xm + r * 64) * XS_STR + xk4 + 2] = xv.z;
            Xs[(xm + r * 64) * XS_STR + xk4 + 3] = xv.w;
            *reinterpret_cast<uint4*>(&Ws[(wk + r * 8) * WS_STR + wn4]) = cvt4(wpre[r]);
        }
        __syncthreads();

        // prefetch next tile (overlaps with mma below)
        if (k0 + 16 < HIDD) {
            #pragma unroll
            for (int r = 0; r < 2; r++) {
                xpre[r] = *reinterpret_cast<const float4*>(
                    &X[(size_t)(m0 + xm + r * 64) * HIDD + k0 + 16 + xk4]);
                wpre[r] = *reinterpret_cast<const float4*>(
                    &Wm[(size_t)(k0 + 16 + wk + r * 8) * HIDD + n0 + wn4]);
            }
        }

        #pragma unroll
        for (int ks = 0; ks < 2; ks++) {
            int kb = ks * 8;
            unsigned a[2][4];
            #pragma unroll
            for (int mt = 0; mt < 2; mt++) {
                int mrow = wrr * 32 + mt * 16;
                a[mt][0] = Xs[(mrow + gid    ) * XS_STR + kb + tin];
                a[mt][1] = Xs[(mrow + gid + 8) * XS_STR + kb + tin];
                a[mt][2] = Xs[(mrow + gid    ) * XS_STR + kb + tin + 4];
                a[mt][3] = Xs[(mrow + gid + 8) * XS_STR + kb + tin + 4];
            }
            #pragma unroll
            for (int nt = 0; nt < 8; nt++) {
                int nn = wcc * 64 + nt * 8;
                unsigned b0 = Ws[(kb + tin    ) * WS_STR + nn + gid];
                unsigned b1 = Ws[(kb + tin + 4) * WS_STR + nn + gid];
                mma8(c[0][nt], a[0], b0, b1);
                mma8(c[1][nt], a[1], b0, b1);
            }
        }
        __syncthreads();
    }

    // epilogue: + bias
    #pragma unroll
    for (int mt = 0; mt < 2; mt++) {
        int r0 = m0 + wrr * 32 + mt * 16 + gid;
        #pragma unroll
        for (int nt = 0; nt < 8; nt++) {
            int col = n0 + wcc * 64 + nt * 8 + 2 * tin;
            float b0 = bias[col], b1 = bias[col + 1];
            float2* p0 = reinterpret_cast<float2*>(&out[(size_t)r0 * HIDD + col]);
            *p0 = make_float2(c[mt][nt][0] + b0, c[mt][nt][1] + b1);
            float2* p1 = reinterpret_cast<float2*>(&out[(size_t)(r0 + 8) * HIDD + col]);
            *p1 = make_float2(c[mt][nt][2] + b0, c[mt][nt][3] + b1);
        }
    }
}

// ---------------------------------------------------------------------------
// Fused attention (tf32 tensor), 512 threads / 16 warps, warp grid 4x4:
//   wr = w>>2 : query-row group (16 rows each, 64 total)
//   wc = w&3  : column quarter
// per key tile: S_all[64,192] = Q @ [K;E]^T ; combine+exp -> P ; O += P@V
// ---------------------------------------------------------------------------
#define QK_STR 68    // 68 mod 32 = 4 -> row-major [row][k] frag conflict-free
#define V_STR  72    // 72 mod 32 = 8 -> [k][n] B-frag conflict-free
#define S_STR  196   // 196 mod 32 = 4 -> P A-frag conflict-free

// word offsets in dynamic smem
#define OFF_Q   0
#define OFF_K   (OFF_Q + 64 * QK_STR)            // 4352
#define OFF_E   (OFF_K + 64 * QK_STR)            // 8704
#define OFF_V   (OFF_E + 128 * QK_STR)           // 17408
#define OFF_S   (OFF_V + 64 * V_STR)             // 22016
#define OFF_MS  (OFF_S + 64 * S_STR)             // 34560
#define OFF_SK  (OFF_MS + 64)
#define OFF_RS  (OFF_SK + 64)
#define OFF_RSUM (OFF_RS + 64 * 9)
#define SMEM_WORDS (OFF_RSUM + 64)               // 35328 words = 141312 B

__global__ __launch_bounds__(512) void attn_kernel(
    const float* __restrict__ amask,   // [B,S]
    const int*   __restrict__ skim,    // [B,S]
    const float* __restrict__ dist,    // [2*MAXP-1, D]
    float*       __restrict__ out)     // [B,S,HID]
{
    extern __shared__ unsigned smw[];
    unsigned* uQ = smw + OFF_Q;
    unsigned* uK = smw + OFF_K;
    unsigned* uE = smw + OFF_E;
    unsigned* uV = smw + OFF_V;
    float* fS   = reinterpret_cast<float*>(smw + OFF_S);
    float* Ms   = reinterpret_cast<float*>(smw + OFF_MS);
    float* Sk   = reinterpret_cast<float*>(smw + OFF_SK);
    float* RS   = reinterpret_cast<float*>(smw + OFF_RS);
    float* Rsum = reinterpret_cast<float*>(smw + OFF_RSUM);

    const int l0 = blockIdx.x * 64;
    const int h  = blockIdx.y;
    const int b  = blockIdx.z;
    const int tid = threadIdx.x;
    const int lane = tid & 31, w = tid >> 5;
    const int wr = w >> 2, wc = w & 3;           // 4x4 warp grid
    const int gid = lane >> 2, tin = lane & 3;
    const int mrow = 16 * wr;

    const float* Qg = g_q + (size_t)b * SS * HIDD + h * DD;
    const float* Kg = g_k + (size_t)b * SS * HIDD + h * DD;
    const float* Vg = g_v + (size_t)b * SS * HIDD + h * DD;

    // Q tile once (tf32): 1024 float4 / 512 threads = 2 iters
    #pragma unroll
    for (int r = 0; r < 2; r++) {
        int idx = tid + r * 512;
        int li = idx >> 4, d4 = (idx & 15) * 4;
        float4 v = *reinterpret_cast<const float4*>(
            &Qg[(size_t)(l0 + li) * HIDD + d4]);
        *reinterpret_cast<uint4*>(&uQ[li * QK_STR + d4]) = cvt4(v);
    }

    const int li_c = tid & 63, cb = tid >> 6;    // combine mapping (8 cols/thread)
    float rs = 0.f;

    float cO[2][4];
    #pragma unroll
    for (int nt = 0; nt < 2; nt++)
        #pragma unroll
        for (int u = 0; u < 4; u++) cO[nt][u] = 0.f;

    for (int r0 = 0; r0 < SS; r0 += 64) {
        __syncthreads();   // prior iter's smem reads complete

        // K, V tiles (tf32)
        #pragma unroll
        for (int r = 0; r < 2; r++) {
            int idx = tid + r * 512;
            int ri = idx >> 4, d4 = (idx & 15) * 4;
            float4 kv = *reinterpret_cast<const float4*>(
                &Kg[(size_t)(r0 + ri) * HIDD + d4]);
            *reinterpret_cast<uint4*>(&uK[ri * QK_STR + d4]) = cvt4(kv);
            float4 vv = *reinterpret_cast<const float4*>(
                &Vg[(size_t)(r0 + ri) * HIDD + d4]);
            *reinterpret_cast<uint4*>(&uV[ri * V_STR + d4]) = cvt4(vv);
        }
        // E band: 128 rows (e=0..127), global row = base+e, only e<=126 used
        int base = l0 - r0 + MAXP - 1 - 63;
        #pragma unroll
        for (int r = 0; r < 4; r++) {
            int idx = tid + r * 512;
            int e = idx >> 4, d4 = (idx & 15) * 4;
            int g = base + e;
            float4 v = make_float4(0.f, 0.f, 0.f, 0.f);
            if (g < 2 * MAXP - 1)
                v = *reinterpret_cast<const float4*>(&dist[(size_t)g * DD + d4]);
            *reinterpret_cast<uint4*>(&uE[e * QK_STR + d4]) = cvt4(v);
        }
        if (tid < 64) {
            Ms[tid] = amask[b * SS + r0 + tid];
            Sk[tid] = (float)skim[b * SS + r0 + tid];
        }
        __syncthreads();

        // ---- S_all = Q @ [K;E]^T : warp = rows 16*wr, cols 48*wc..+47 ----
        float cS[6][4];
        #pragma unroll
        for (int nt = 0; nt < 6; nt++)
            #pragma unroll
            for (int u = 0; u < 4; u++) cS[nt][u] = 0.f;

        #pragma unroll
        for (int ks = 0; ks < 8; ks++) {
            int kb = ks * 8;
            unsigned a[4];
            a[0] = uQ[(mrow + gid    ) * QK_STR + kb + tin];
            a[1] = uQ[(mrow + gid + 8) * QK_STR + kb + tin];
            a[2] = uQ[(mrow + gid    ) * QK_STR + kb + tin + 4];
            a[3] = uQ[(mrow + gid + 8) * QK_STR + kb + tin + 4];
            #pragma unroll
            for (int nt = 0; nt < 6; nt++) {
                int n0 = wc * 48 + nt * 8;
                const unsigned* brow = (n0 < 64)
                    ? &uK[(n0 + gid) * QK_STR]
                    : &uE[(n0 - 64 + gid) * QK_STR];
                mma8(cS[nt], a, brow[kb + tin], brow[kb + tin + 4]);
            }
        }
        // write S to smem
        #pragma unroll
        for (int nt = 0; nt < 6; nt++) {
            int n0 = wc * 48 + nt * 8 + 2 * tin;
            *reinterpret_cast<float2*>(&fS[(mrow + gid) * S_STR + n0]) =
                make_float2(cS[nt][0], cS[nt][1]);
            *reinterpret_cast<float2*>(&fS[(mrow + gid + 8) * S_STR + n0]) =
                make_float2(cS[nt][2], cS[nt][3]);
        }
        __syncthreads();

        // ---- combine + exp -> P (in place, tf32, cols 0..63; 8 cols/thread) ----
        {
            float* Srow = &fS[li_c * S_STR];
            #pragma unroll
            for (int jj = 0; jj < 2; jj++) {
                int j = cb * 8 + jj * 4;
                float4 s1 = *reinterpret_cast<const float4*>(&Srow[j]);
                float s1a[4] = {s1.x, s1.y, s1.z, s1.w};
                float pv[4];
                #pragma unroll
                for (int u = 0; u < 4; u++) {
                    int ri = j + u;
                    float s2 = Srow[64 + li_c - ri + 63];
                    float p = __expf((s1a[u] + s2) * 0.125f + Ms[ri]) * Sk[ri];
                    rs += p;
                    pv[u] = __uint_as_float(f2tf(p));
                }
                *reinterpret_cast<float4*>(&Srow[j]) =
                    make_float4(pv[0], pv[1], pv[2], pv[3]);
            }
        }
        __syncthreads();

        // ---- O += P @ V : warp = rows 16*wr, cols 16*wc..+15 ----
        const unsigned* Pb = reinterpret_cast<const unsigned*>(fS);
        #pragma unroll
        for (int ks = 0; ks < 8; ks++) {
            int kb = ks * 8;
            unsigned a[4];
            a[0] = Pb[(mrow + gid    ) * S_STR + kb + tin];
            a[1] = Pb[(mrow + gid + 8) * S_STR + kb + tin];
            a[2] = Pb[(mrow + gid    ) * S_STR + kb + tin + 4];
            a[3] = Pb[(mrow + gid + 8) * S_STR + kb + tin + 4];
            #pragma unroll
            for (int nt = 0; nt < 2; nt++) {
                int n0 = wc * 16 + nt * 8;
                unsigned b0 = uV[(kb + tin    ) * V_STR + n0 + gid];
                unsigned b1 = uV[(kb + tin + 4) * V_STR + n0 + gid];
                mma8(cO[nt], a, b0, b1);
            }
        }
    }

    __syncthreads();
    RS[li_c * 9 + cb] = rs;
    __syncthreads();
    if (tid < 64) {
        float s = 1e-8f;
        #pragma unroll
        for (int t = 0; t < 8; t++) s += RS[tid * 9 + t];
        Rsum[tid] = 1.0f / s;
    }
    __syncthreads();

    // write O
    float inv0 = Rsum[mrow + gid], inv1 = Rsum[mrow + gid + 8];
    #pragma unroll
    for (int nt = 0; nt < 2; nt++) {
        int col = h * DD + wc * 16 + nt * 8 + 2 * tin;
        size_t g0 = (size_t)(b * SS + l0 + mrow + gid) * HIDD + col;
        size_t g1 = (size_t)(b * SS + l0 + mrow + gid + 8) * HIDD + col;
        *reinterpret_cast<float2*>(&out[g0]) =
            make_float2(cO[nt][0] * inv0, cO[nt][1] * inv0);
        *reinterpret_cast<float2*>(&out[g1]) =
            make_float2(cO[nt][2] * inv1, cO[nt][3] * inv1);
    }
}

// ---------------------------------------------------------------------------
extern "C" void kernel_launch(void* const* d_in, const int* in_sizes, int n_in,
                              void* d_out, int out_size)
{
    const float* hs    = (const float*)d_in[0];
    const float* amask = (const float*)d_in[1];
    const int*   skim  = (const int*)  d_in[2];
    const float* Wq    = (const float*)d_in[3];
    const float* bq    = (const float*)d_in[4];
    const float* Wk    = (const float*)d_in[5];
    const float* bk    = (const float*)d_in[6];
    const float* Wv    = (const float*)d_in[7];
    const float* bv    = (const float*)d_in[8];
    const float* dist  = (const float*)d_in[9];
    float* out = (float*)d_out;

    dim3 gg(HIDD / 128, (BB * SS) / 128, 3);   // (8, 32, 3)
    qkv_gemm<<<gg, 256>>>(hs, Wq, bq, Wk, bk, Wv, bv);

    size_t smem = (size_t)SMEM_WORDS * sizeof(unsigned);
    cudaFuncSetAttribute(attn_kernel, cudaFuncAttributeMaxDynamicSharedMemorySize, (int)smem);
    dim3 ga(SS / 64, HH, BB);                  // (16, 16, 4)
    attn_kernel<<<ga, 512, smem>>>(amask, skim, dist, out);
}